// round 9
// baseline (speedup 1.0000x reference)
#include <cuda_runtime.h>
#include <cuda_fp16.h>

#define EMBED_DIM   256
#define NUM_EDGES   16384
#define NUM_NODES   100000
#define NTHREADS    128
#define WARPS_CTA   (NTHREADS / 32)

#define CONV_GROUPS (NUM_NODES * EMBED_DIM / 8)   // 3,200,000 groups of 8 floats
#define CONV_BLOCKS (CONV_GROUPS / 256)           // 12,500

// fp16 shadow of the embedding table (51.2 MB) — sanctioned __device__ scratch.
__device__ __half g_emb_h[(size_t)NUM_NODES * EMBED_DIM];
// g_offs[e] = lower_bound(seg, e); g_offs[NUM_EDGES] = total.
__device__ int g_offs[NUM_EDGES + 1];

__device__ __forceinline__ unsigned h2_bits(__half2 h)
{
    unsigned u;
    *reinterpret_cast<__half2*>(&u) = h;
    return u;
}

// Fused prepass: blocks [0, CONV_BLOCKS) convert fp32 -> fp16;
// remaining blocks do the diff-based segment boundary fill.
__global__ void __launch_bounds__(256)
prep_kernel(const float* __restrict__ emb, const int* __restrict__ seg, int total)
{
    const int b = blockIdx.x;
    if (b < CONV_BLOCKS) {
        const int i = b * 256 + threadIdx.x;           // group of 8 floats
        const float4* src = (const float4*)emb;
        float4 a = __ldcs(src + 2 * (size_t)i);
        float4 c = __ldcs(src + 2 * (size_t)i + 1);
        uint4 o;
        o.x = h2_bits(__floats2half2_rn(a.x, a.y));
        o.y = h2_bits(__floats2half2_rn(a.z, a.w));
        o.z = h2_bits(__floats2half2_rn(c.x, c.y));
        o.w = h2_bits(__floats2half2_rn(c.z, c.w));
        ((uint4*)g_emb_h)[i] = o;
    } else {
        const int i = (b - CONV_BLOCKS) * 256 + threadIdx.x;
        if (i >= total) return;
        int cur = seg[i];
        if (i == 0) {
            for (int e = 0; e <= cur; e++) g_offs[e] = 0;
        } else {
            int prev = seg[i - 1];
            for (int e = prev + 1; e <= cur; e++) g_offs[e] = i;
        }
        if (i == total - 1) {
            for (int e = cur + 1; e <= NUM_EDGES; e++) g_offs[e] = total;
        }
    }
}

// 32-byte gather with L2 evict_last (keep the 51MB fp16 table L2-resident).
__device__ __forceinline__ ulonglong4 ldg_el8(const ulonglong4* p)
{
    ulonglong4 v;
    asm volatile("ld.global.nc.L2::evict_last.v4.b64 {%0,%1,%2,%3}, [%4];"
                 : "=l"(v.x), "=l"(v.y), "=l"(v.z), "=l"(v.w)
                 : "l"(p));
    return v;
}

__device__ __forceinline__ int ldg_cs(const int* p)
{
    int v;
    asm volatile("ld.global.cs.b32 %0, [%1];" : "=r"(v) : "l"(p));
    return v;
}

__device__ __forceinline__ void stg_cs8(ulonglong4* p, const ulonglong4 v)
{
    asm volatile("st.global.cs.v4.b64 [%0], {%1,%2,%3,%4};"
                 :: "l"(p), "l"(v.x), "l"(v.y), "l"(v.z), "l"(v.w));
}

// Accumulate 16 fp16 values (one 32B chunk) into fp32 accumulators.
__device__ __forceinline__ void acch(float* a, const ulonglong4 v)
{
    const __half2* h = (const __half2*)&v;
#pragma unroll
    for (int k = 0; k < 8; k++) {
        float2 f = __half22float2(h[k]);
        a[2 * k]     += f.x;
        a[2 * k + 1] += f.y;
    }
}

// One WARP per hyperedge on the fp16 table. fp16 row = 512B = 16 x 32B chunks,
// so one 256-bit load instruction covers TWO members per warp:
//   s = lane>>4 selects member j+s of the pair, c = lane&15 selects the chunk.
// fp32 accumulation; halves combined via shfl.xor(16) at the end.
__global__ void __launch_bounds__(NTHREADS)
agg_kernel(const int* __restrict__ nidx,   // [TOTAL]
           float*     __restrict__ out)    // [NUM_EDGES, 256]
{
    const int lane = threadIdx.x & 31;
    const int e    = blockIdx.x * WARPS_CTA + (threadIdx.x >> 5);
    const int s    = lane >> 4;
    const int c    = lane & 15;

    const int lo = g_offs[e];
    const int hi = g_offs[e + 1];

    const ulonglong4* __restrict__ rows = (const ulonglong4*)g_emb_h; // 16 chunks/row

    float acc[16];
#pragma unroll
    for (int k = 0; k < 16; k++) acc[k] = 0.0f;

    // Pipelined index loads: prefetch next chunk while gathering current.
    int myidx = 0;
    if (lo + lane < hi) myidx = ldg_cs(nidx + lo + lane);

    for (int base = lo; base < hi; base += 32) {
        const int cnt = min(32, hi - base);
        const int cur = myidx;
        if (base + 32 + lane < hi) myidx = ldg_cs(nidx + base + 32 + lane);

        int j = 0;
        // 8 members (4 pairs) per iteration -> 4 independent 32B gathers/lane.
        for (; j + 7 < cnt; j += 8) {
            const int n0 = __shfl_sync(0xffffffffu, cur, j + s);
            const int n1 = __shfl_sync(0xffffffffu, cur, j + 2 + s);
            const int n2 = __shfl_sync(0xffffffffu, cur, j + 4 + s);
            const int n3 = __shfl_sync(0xffffffffu, cur, j + 6 + s);
            ulonglong4 v0 = ldg_el8(rows + (size_t)n0 * 16 + c);
            ulonglong4 v1 = ldg_el8(rows + (size_t)n1 * 16 + c);
            ulonglong4 v2 = ldg_el8(rows + (size_t)n2 * 16 + c);
            ulonglong4 v3 = ldg_el8(rows + (size_t)n3 * 16 + c);
            acch(acc, v0);
            acch(acc, v1);
            acch(acc, v2);
            acch(acc, v3);
        }
        for (; j + 1 < cnt; j += 2) {
            const int n = __shfl_sync(0xffffffffu, cur, j + s);
            acch(acc, ldg_el8(rows + (size_t)n * 16 + c));
        }
        if (j < cnt) {  // odd tail: only the s==0 half-warp contributes
            const int n = __shfl_sync(0xffffffffu, cur, j);
            if (s == 0) acch(acc, ldg_el8(rows + (size_t)n * 16 + c));
        }
    }

    // Combine the two member-pair halves (lane l <-> lane l^16 hold same columns).
#pragma unroll
    for (int k = 0; k < 16; k++)
        acc[k] += __shfl_xor_sync(0xffffffffu, acc[k], 16);

    const int cnt = hi - lo;
    const float inv = 1.0f / (float)(cnt > 0 ? cnt : 1);
#pragma unroll
    for (int k = 0; k < 16; k++) acc[k] *= inv;

    // Lanes 0..15 each own fp32 columns [16c, 16c+16) = output chunks 2c, 2c+1.
    if (s == 0) {
        ulonglong4 r0, r1;
        float* f0 = (float*)&r0;
        float* f1 = (float*)&r1;
#pragma unroll
        for (int k = 0; k < 8; k++) { f0[k] = acc[k]; f1[k] = acc[8 + k]; }
        ulonglong4* o = (ulonglong4*)out + (size_t)e * 32 + 2 * c;
        stg_cs8(o,     r0);
        stg_cs8(o + 1, r1);
    }
}

extern "C" void kernel_launch(void* const* d_in, const int* in_sizes, int n_in,
                              void* d_out, int out_size)
{
    const float* emb  = (const float*)d_in[0];
    const int*   nidx = (const int*)d_in[1];
    const int*   seg  = (const int*)d_in[2];
    float*       out  = (float*)d_out;
    const int total = in_sizes[1];

    const int bounds_blocks = (total + 255) / 256;
    prep_kernel<<<CONV_BLOCKS + bounds_blocks, 256>>>(emb, seg, total);
    agg_kernel<<<NUM_EDGES / WARPS_CTA, NTHREADS>>>(nidx, out);
}